// round 1
// baseline (speedup 1.0000x reference)
#include <cuda_runtime.h>

// Problem constants (fixed by the reference setup_inputs)
#define N_NODES 50000
#define HID     64
#define NE      800000
#define NPRED   100000
#define NL      2
#define BN_EPS  1e-5f

// ---------------- scratch (static __device__ — no allocations allowed) ------
__device__ float g_deg[N_NODES];
__device__ float g_dis[N_NODES];
__device__ float g_x  [N_NODES * HID];
__device__ float g_h  [N_NODES * HID];
__device__ float g_agg[N_NODES * HID];
__device__ float g_sums [HID];
__device__ float g_sumsq[HID];
__device__ float g_mu   [HID];
__device__ float g_scale[HID];

// ---------------- degree / norm --------------------------------------------
__global__ void k_deg_init() {
    int i = blockIdx.x * 256 + threadIdx.x;
    if (i < N_NODES) g_deg[i] = 1.0f;   // self-loop
}

__global__ void k_deg_count(const int* __restrict__ col) {
    int e = blockIdx.x * 256 + threadIdx.x;
    if (e < NE) atomicAdd(&g_deg[col[e]], 1.0f);
}

__global__ void k_dis() {
    int i = blockIdx.x * 256 + threadIdx.x;
    if (i < N_NODES) g_dis[i] = rsqrtf(g_deg[i]);
}

// ---------------- input projection: x = [id|n2v] @ Wp + bp ------------------
// block = 256 threads, handles 64 rows (16 rows per inner tile).
__global__ void k_proj(const float* __restrict__ id_emb,
                       const float* __restrict__ n2v,
                       const float* __restrict__ W,   // [128,64] row-major
                       const float* __restrict__ b) {
    __shared__ float4 sW[128 * 16];        // 32 KB
    __shared__ float  sX[16][128];         // 8 KB
    int tid = threadIdx.x;
    for (int i = tid; i < 128 * 16; i += 256) sW[i] = ((const float4*)W)[i];

    int rr = tid >> 4;            // 0..15 row in tile
    int cq = tid & 15;            // float4 column group
    const float4 b4 = ((const float4*)b)[cq];
    int base = blockIdx.x * 64;

    for (int t = 0; t < 64; t += 16) {
        __syncthreads();
        int row0 = base + t;
        for (int i = tid; i < 16 * 128; i += 256) {
            int r = i >> 7, k = i & 127;
            int row = row0 + r;
            float v = 0.0f;
            if (row < N_NODES) v = (k < 64) ? id_emb[row * 64 + k] : n2v[row * 64 + (k - 64)];
            sX[r][k] = v;
        }
        __syncthreads();
        int row = row0 + rr;
        if (row < N_NODES) {
            float4 acc = b4;
            #pragma unroll 16
            for (int k = 0; k < 128; k++) {
                float  xv = sX[rr][k];
                float4 w  = sW[k * 16 + cq];
                acc.x += xv * w.x; acc.y += xv * w.y;
                acc.z += xv * w.z; acc.w += xv * w.w;
            }
            ((float4*)g_x)[row * 16 + cq] = acc;
        }
    }
}

// ---------------- h = x @ conv_w[l] (64x64) ---------------------------------
__global__ void k_gemm64(const float* __restrict__ W) {
    __shared__ float4 sW[64 * 16];         // 16 KB
    __shared__ float  sX[16][64];          // 4 KB
    int tid = threadIdx.x;
    for (int i = tid; i < 64 * 16; i += 256) sW[i] = ((const float4*)W)[i];

    int rr = tid >> 4;
    int cq = tid & 15;
    int base = blockIdx.x * 64;

    for (int t = 0; t < 64; t += 16) {
        __syncthreads();
        int row0 = base + t;
        for (int i = tid; i < 16 * 64; i += 256) {
            int r = i >> 6, k = i & 63;
            int row = row0 + r;
            sX[r][k] = (row < N_NODES) ? g_x[row * 64 + k] : 0.0f;
        }
        __syncthreads();
        int row = row0 + rr;
        if (row < N_NODES) {
            float4 acc = make_float4(0.f, 0.f, 0.f, 0.f);
            #pragma unroll 16
            for (int k = 0; k < 64; k++) {
                float  xv = sX[rr][k];
                float4 w  = sW[k * 16 + cq];
                acc.x += xv * w.x; acc.y += xv * w.y;
                acc.z += xv * w.z; acc.w += xv * w.w;
            }
            ((float4*)g_h)[row * 16 + cq] = acc;
        }
    }
}

// ---------------- agg = self-loop contribution + bias; zero BN stats --------
__global__ void k_init_agg(const float* __restrict__ convb) {
    int idx = blockIdx.x * 256 + threadIdx.x;
    if (blockIdx.x == 0 && threadIdx.x < 64) {
        g_sums[threadIdx.x]  = 0.0f;
        g_sumsq[threadIdx.x] = 0.0f;
    }
    if (idx >= N_NODES * 16) return;
    int i  = idx >> 4;
    int cq = idx & 15;
    float d  = g_dis[i];
    float d2 = d * d;                       // dis[i]^2 = 1/deg
    float4 h = ((const float4*)g_h)[idx];
    float4 b = ((const float4*)convb)[cq];
    float4 o = make_float4(h.x * d2 + b.x, h.y * d2 + b.y,
                           h.z * d2 + b.z, h.w * d2 + b.w);
    ((float4*)g_agg)[idx] = o;
}

// ---------------- edge scatter: agg[col] += norm * h[row] -------------------
// 16 threads per edge, one float4 lane each (coalesced gather, vector RED).
__global__ void k_scatter(const int* __restrict__ row,
                          const int* __restrict__ col) {
    long long gid = (long long)blockIdx.x * 256 + threadIdx.x;
    int e = (int)(gid >> 4);
    int l = (int)(gid & 15);
    if (e >= NE) return;
    int r = row[e];
    int c = col[e];
    float w = g_dis[r] * g_dis[c];
    float4 v = ((const float4*)g_h)[r * 16 + l];
    float4 u = make_float4(v.x * w, v.y * w, v.z * w, v.w * w);
#if defined(__CUDA_ARCH__) && (__CUDA_ARCH__ >= 900)
    atomicAdd(((float4*)g_agg) + c * 16 + l, u);
#else
    float* p = g_agg + c * 64 + l * 4;
    atomicAdd(p + 0, u.x); atomicAdd(p + 1, u.y);
    atomicAdd(p + 2, u.z); atomicAdd(p + 3, u.w);
#endif
}

// ---------------- BatchNorm stats (sum, sumsq per channel) ------------------
__global__ void k_bnstats() {
    int c = threadIdx.x & 63;
    int g = threadIdx.x >> 6;               // 4 row-groups per block
    float s = 0.0f, q = 0.0f;
    for (int i = blockIdx.x * 4 + g; i < N_NODES; i += gridDim.x * 4) {
        float v = g_agg[i * 64 + c];
        s += v; q += v * v;
    }
    __shared__ float ss[4][64], sq[4][64];
    ss[g][c] = s; sq[g][c] = q;
    __syncthreads();
    if (g == 0) {
        s = ss[0][c] + ss[1][c] + ss[2][c] + ss[3][c];
        q = sq[0][c] + sq[1][c] + sq[2][c] + sq[3][c];
        atomicAdd(&g_sums[c], s);
        atomicAdd(&g_sumsq[c], q);
    }
}

__global__ void k_bnfinal(const float* __restrict__ gamma) {
    int c = threadIdx.x;
    const float inv_n = 1.0f / (float)N_NODES;
    float mu  = g_sums[c] * inv_n;
    float var = g_sumsq[c] * inv_n - mu * mu;
    g_mu[c]    = mu;
    g_scale[c] = rsqrtf(var + BN_EPS) * gamma[c];
}

// ---------------- x = x + relu(BN(agg)) -------------------------------------
__global__ void k_apply(const float* __restrict__ beta) {
    int idx = blockIdx.x * 256 + threadIdx.x;
    if (idx >= N_NODES * 16) return;
    int cq = idx & 15;
    float4 a  = ((const float4*)g_agg)[idx];
    float4 x  = ((float4*)g_x)[idx];
    float4 mu = ((const float4*)g_mu)[cq];
    float4 sc = ((const float4*)g_scale)[cq];
    float4 bt = ((const float4*)beta)[cq];
    x.x += fmaxf((a.x - mu.x) * sc.x + bt.x, 0.0f);
    x.y += fmaxf((a.y - mu.y) * sc.y + bt.y, 0.0f);
    x.z += fmaxf((a.z - mu.z) * sc.z + bt.z, 0.0f);
    x.w += fmaxf((a.w - mu.w) * sc.w + bt.w, 0.0f);
    ((float4*)g_x)[idx] = x;
}

// ---------------- link decoder: out[p] = dot(z[a], z[b]) --------------------
__global__ void k_decode(const int* __restrict__ pred, float* __restrict__ out) {
    long long gid = (long long)blockIdx.x * 256 + threadIdx.x;
    int p = (int)(gid >> 4);
    int l = (int)(gid & 15);
    if (p >= NPRED) return;
    int a = pred[2 * p];
    int b = pred[2 * p + 1];
    float4 va = ((const float4*)g_x)[a * 16 + l];
    float4 vb = ((const float4*)g_x)[b * 16 + l];
    float s = va.x * vb.x + va.y * vb.y + va.z * vb.z + va.w * vb.w;
    s += __shfl_xor_sync(0xffffffffu, s, 8);
    s += __shfl_xor_sync(0xffffffffu, s, 4);
    s += __shfl_xor_sync(0xffffffffu, s, 2);
    s += __shfl_xor_sync(0xffffffffu, s, 1);
    if (l == 0) out[p] = s;
}

// ---------------- launch ----------------------------------------------------
extern "C" void kernel_launch(void* const* d_in, const int* in_sizes, int n_in,
                              void* d_out, int out_size) {
    const int*   edge    = (const int*)  d_in[0];   // [2, NE]
    const int*   pred    = (const int*)  d_in[1];   // [NPRED, 2]
    const float* id_emb  = (const float*)d_in[2];   // [N, 64]
    const float* n2v     = (const float*)d_in[3];   // [N, 64]
    const float* proj_w  = (const float*)d_in[4];   // [128, 64]
    const float* proj_b  = (const float*)d_in[5];   // [64]
    const float* conv_w  = (const float*)d_in[6];   // [2, 64, 64]
    const float* conv_b  = (const float*)d_in[7];   // [2, 64]
    const float* gamma   = (const float*)d_in[8];   // [2, 64]
    const float* beta    = (const float*)d_in[9];   // [2, 64]
    float* out = (float*)d_out;

    const int TB = 256;
    k_deg_init <<<(N_NODES + TB - 1) / TB, TB>>>();
    k_deg_count<<<(NE + TB - 1) / TB, TB>>>(edge + NE);
    k_dis      <<<(N_NODES + TB - 1) / TB, TB>>>();
    k_proj     <<<(N_NODES + 63) / 64, TB>>>(id_emb, n2v, proj_w, proj_b);

    for (int l = 0; l < NL; l++) {
        k_gemm64  <<<(N_NODES + 63) / 64, TB>>>(conv_w + l * HID * HID);
        k_init_agg<<<(N_NODES * 16 + TB - 1) / TB, TB>>>(conv_b + l * HID);
        k_scatter <<<(NE * 16 + TB - 1) / TB, TB>>>(edge, edge + NE);
        k_bnstats <<<256, TB>>>();
        k_bnfinal <<<1, 64>>>(gamma + l * HID);
        k_apply   <<<(N_NODES * 16 + TB - 1) / TB, TB>>>(beta + l * HID);
    }

    k_decode<<<((long long)NPRED * 16 + TB - 1) / TB, TB>>>(pred, out);
}

// round 2
// speedup vs baseline: 1.1514x; 1.1514x over previous
#include <cuda_runtime.h>

// Problem constants (fixed by the reference setup_inputs)
#define N_NODES 50000
#define HID     64
#define NE      800000
#define NPRED   100000
#define NL      2
#define BN_EPS  1e-5f

// ---------------- scratch (static __device__ — no allocations allowed) ------
__device__ float g_deg[N_NODES];
__device__ float g_dis[N_NODES];
__device__ float g_x  [N_NODES * HID];
__device__ float g_h  [N_NODES * HID];
__device__ float g_agg[N_NODES * HID];
__device__ float g_sums [HID];
__device__ float g_sumsq[HID];
__device__ float g_mu   [HID];
__device__ float g_scale[HID];

// ---------------- degree / norm --------------------------------------------
__global__ void k_deg_init() {
    int i = blockIdx.x * 256 + threadIdx.x;
    if (i < N_NODES) g_deg[i] = 1.0f;   // self-loop
}

__global__ void k_deg_count(const int* __restrict__ col) {
    int e = blockIdx.x * 256 + threadIdx.x;
    if (e < NE) atomicAdd(&g_deg[col[e]], 1.0f);
}

__global__ void k_dis() {
    int i = blockIdx.x * 256 + threadIdx.x;
    if (i < N_NODES) g_dis[i] = rsqrtf(g_deg[i]);
}

// ---------------- input projection: x = [id|n2v] @ Wp + bp ------------------
// One thread per row; 64 register accumulators; W broadcast from shared.
__global__ __launch_bounds__(128) void k_proj(const float* __restrict__ id_emb,
                                              const float* __restrict__ n2v,
                                              const float* __restrict__ W,   // [128,64]
                                              const float* __restrict__ b) {
    __shared__ float4 sW[128 * 16];   // 32 KB
    int tid = threadIdx.x;
    for (int i = tid; i < 128 * 16; i += 128) sW[i] = ((const float4*)W)[i];
    __syncthreads();

    int row = blockIdx.x * 128 + tid;
    if (row >= N_NODES) return;

    float4 acc[16];
    #pragma unroll
    for (int q = 0; q < 16; q++) acc[q] = ((const float4*)b)[q];

    const float4* xa = (const float4*)(id_emb + (size_t)row * 64);
    const float4* xb = (const float4*)(n2v    + (size_t)row * 64);

    #pragma unroll 4
    for (int k4 = 0; k4 < 32; k4++) {
        float4 xv4 = (k4 < 16) ? xa[k4] : xb[k4 - 16];
        float xs[4] = {xv4.x, xv4.y, xv4.z, xv4.w};
        #pragma unroll
        for (int j = 0; j < 4; j++) {
            float xv = xs[j];
            const float4* wrow = &sW[(k4 * 4 + j) * 16];
            #pragma unroll
            for (int q = 0; q < 16; q++) {
                float4 w = wrow[q];
                acc[q].x += xv * w.x; acc[q].y += xv * w.y;
                acc[q].z += xv * w.z; acc[q].w += xv * w.w;
            }
        }
    }
    float4* out = (float4*)(g_x + (size_t)row * 64);
    #pragma unroll
    for (int q = 0; q < 16; q++) out[q] = acc[q];
}

// ---------------- fused per-layer GEMM --------------------------------------
// Optionally applies previous layer's BN+ReLU+residual to x first (in-place),
// then h = x @ W, writes g_h and g_agg = h/deg + conv_b, zeroes BN stats.
__global__ __launch_bounds__(128) void k_layer_gemm(const float* __restrict__ W,  // [64,64]
                                                    const float* __restrict__ convb,
                                                    const float* __restrict__ beta_prev,
                                                    int apply_prev) {
    __shared__ float4 sW[64 * 16];    // 16 KB
    int tid = threadIdx.x;
    for (int i = tid; i < 64 * 16; i += 128) sW[i] = ((const float4*)W)[i];
    __syncthreads();

    if (blockIdx.x == 0 && tid < 64) { g_sums[tid] = 0.0f; g_sumsq[tid] = 0.0f; }

    int row = blockIdx.x * 128 + tid;
    if (row >= N_NODES) return;

    float4* xrow = (float4*)(g_x + (size_t)row * 64);
    float4 xr[16];
    #pragma unroll
    for (int q = 0; q < 16; q++) xr[q] = xrow[q];

    if (apply_prev) {
        const float4* arow = (const float4*)(g_agg + (size_t)row * 64);
        #pragma unroll
        for (int q = 0; q < 16; q++) {
            float4 a  = arow[q];
            float4 mu = ((const float4*)g_mu)[q];
            float4 sc = ((const float4*)g_scale)[q];
            float4 bt = ((const float4*)beta_prev)[q];
            xr[q].x += fmaxf((a.x - mu.x) * sc.x + bt.x, 0.0f);
            xr[q].y += fmaxf((a.y - mu.y) * sc.y + bt.y, 0.0f);
            xr[q].z += fmaxf((a.z - mu.z) * sc.z + bt.z, 0.0f);
            xr[q].w += fmaxf((a.w - mu.w) * sc.w + bt.w, 0.0f);
            xrow[q] = xr[q];
        }
    }

    float4 acc[16];
    #pragma unroll
    for (int q = 0; q < 16; q++) acc[q] = make_float4(0.f, 0.f, 0.f, 0.f);

    #pragma unroll 4
    for (int k4 = 0; k4 < 16; k4++) {
        float xs[4] = {xr[k4].x, xr[k4].y, xr[k4].z, xr[k4].w};
        #pragma unroll
        for (int j = 0; j < 4; j++) {
            float xv = xs[j];
            const float4* wrow = &sW[(k4 * 4 + j) * 16];
            #pragma unroll
            for (int q = 0; q < 16; q++) {
                float4 w = wrow[q];
                acc[q].x += xv * w.x; acc[q].y += xv * w.y;
                acc[q].z += xv * w.z; acc[q].w += xv * w.w;
            }
        }
    }

    float d  = g_dis[row];
    float d2 = d * d;                 // 1/deg (self-loop norm)
    float4* hrow = (float4*)(g_h   + (size_t)row * 64);
    float4* grow = (float4*)(g_agg + (size_t)row * 64);
    #pragma unroll
    for (int q = 0; q < 16; q++) {
        hrow[q] = acc[q];
        float4 bq = ((const float4*)convb)[q];
        grow[q] = make_float4(acc[q].x * d2 + bq.x, acc[q].y * d2 + bq.y,
                              acc[q].z * d2 + bq.z, acc[q].w * d2 + bq.w);
    }
}

// ---------------- edge scatter: agg[col] += norm * h[row] -------------------
__global__ void k_scatter(const int* __restrict__ row,
                          const int* __restrict__ col) {
    long long gid = (long long)blockIdx.x * 256 + threadIdx.x;
    int e = (int)(gid >> 4);
    int l = (int)(gid & 15);
    if (e >= NE) return;
    int r = row[e];
    int c = col[e];
    float w = g_dis[r] * g_dis[c];
    float4 v = ((const float4*)g_h)[r * 16 + l];
    float4 u = make_float4(v.x * w, v.y * w, v.z * w, v.w * w);
#if defined(__CUDA_ARCH__) && (__CUDA_ARCH__ >= 900)
    atomicAdd(((float4*)g_agg) + c * 16 + l, u);
#else
    float* p = g_agg + c * 64 + l * 4;
    atomicAdd(p + 0, u.x); atomicAdd(p + 1, u.y);
    atomicAdd(p + 2, u.z); atomicAdd(p + 3, u.w);
#endif
}

// ---------------- BatchNorm stats (sum, sumsq per channel) ------------------
__global__ void k_bnstats() {
    int c = threadIdx.x & 63;
    int g = threadIdx.x >> 6;               // 4 row-groups per block
    float s = 0.0f, q = 0.0f;
    for (int i = blockIdx.x * 4 + g; i < N_NODES; i += gridDim.x * 4) {
        float v = g_agg[i * 64 + c];
        s += v; q += v * v;
    }
    __shared__ float ss[4][64], sq[4][64];
    ss[g][c] = s; sq[g][c] = q;
    __syncthreads();
    if (g == 0) {
        s = ss[0][c] + ss[1][c] + ss[2][c] + ss[3][c];
        q = sq[0][c] + sq[1][c] + sq[2][c] + sq[3][c];
        atomicAdd(&g_sums[c], s);
        atomicAdd(&g_sumsq[c], q);
    }
}

__global__ void k_bnfinal(const float* __restrict__ gamma) {
    int c = threadIdx.x;
    const float inv_n = 1.0f / (float)N_NODES;
    float mu  = g_sums[c] * inv_n;
    float var = g_sumsq[c] * inv_n - mu * mu;
    g_mu[c]    = mu;
    g_scale[c] = rsqrtf(var + BN_EPS) * gamma[c];
}

// ---------------- final x = x + relu(BN(agg)) -------------------------------
__global__ void k_apply(const float* __restrict__ beta) {
    int idx = blockIdx.x * 256 + threadIdx.x;
    if (idx >= N_NODES * 16) return;
    int cq = idx & 15;
    float4 a  = ((const float4*)g_agg)[idx];
    float4 x  = ((float4*)g_x)[idx];
    float4 mu = ((const float4*)g_mu)[cq];
    float4 sc = ((const float4*)g_scale)[cq];
    float4 bt = ((const float4*)beta)[cq];
    x.x += fmaxf((a.x - mu.x) * sc.x + bt.x, 0.0f);
    x.y += fmaxf((a.y - mu.y) * sc.y + bt.y, 0.0f);
    x.z += fmaxf((a.z - mu.z) * sc.z + bt.z, 0.0f);
    x.w += fmaxf((a.w - mu.w) * sc.w + bt.w, 0.0f);
    ((float4*)g_x)[idx] = x;
}

// ---------------- link decoder: out[p] = dot(z[a], z[b]) --------------------
__global__ void k_decode(const int* __restrict__ pred, float* __restrict__ out) {
    long long gid = (long long)blockIdx.x * 256 + threadIdx.x;
    int p = (int)(gid >> 4);
    int l = (int)(gid & 15);
    if (p >= NPRED) return;
    int a = pred[2 * p];
    int b = pred[2 * p + 1];
    float4 va = ((const float4*)g_x)[a * 16 + l];
    float4 vb = ((const float4*)g_x)[b * 16 + l];
    float s = va.x * vb.x + va.y * vb.y + va.z * vb.z + va.w * vb.w;
    s += __shfl_xor_sync(0xffffffffu, s, 8);
    s += __shfl_xor_sync(0xffffffffu, s, 4);
    s += __shfl_xor_sync(0xffffffffu, s, 2);
    s += __shfl_xor_sync(0xffffffffu, s, 1);
    if (l == 0) out[p] = s;
}

// ---------------- launch ----------------------------------------------------
extern "C" void kernel_launch(void* const* d_in, const int* in_sizes, int n_in,
                              void* d_out, int out_size) {
    const int*   edge    = (const int*)  d_in[0];   // [2, NE]
    const int*   pred    = (const int*)  d_in[1];   // [NPRED, 2]
    const float* id_emb  = (const float*)d_in[2];   // [N, 64]
    const float* n2v     = (const float*)d_in[3];   // [N, 64]
    const float* proj_w  = (const float*)d_in[4];   // [128, 64]
    const float* proj_b  = (const float*)d_in[5];   // [64]
    const float* conv_w  = (const float*)d_in[6];   // [2, 64, 64]
    const float* conv_b  = (const float*)d_in[7];   // [2, 64]
    const float* gamma   = (const float*)d_in[8];   // [2, 64]
    const float* beta    = (const float*)d_in[9];   // [2, 64]
    float* out = (float*)d_out;

    const int TB = 256;
    k_deg_init <<<(N_NODES + TB - 1) / TB, TB>>>();
    k_deg_count<<<(NE + TB - 1) / TB, TB>>>(edge + NE);
    k_dis      <<<(N_NODES + TB - 1) / TB, TB>>>();
    k_proj     <<<(N_NODES + 127) / 128, 128>>>(id_emb, n2v, proj_w, proj_b);

    for (int l = 0; l < NL; l++) {
        k_layer_gemm<<<(N_NODES + 127) / 128, 128>>>(
            conv_w + l * HID * HID, conv_b + l * HID,
            (l > 0) ? (beta + (l - 1) * HID) : nullptr, (l > 0) ? 1 : 0);
        k_scatter <<<(NE * 16 + TB - 1) / TB, TB>>>(edge, edge + NE);
        k_bnstats <<<256, TB>>>();
        k_bnfinal <<<1, 64>>>(gamma + l * HID);
    }

    k_apply <<<(N_NODES * 16 + TB - 1) / TB, TB>>>(beta + (NL - 1) * HID);
    k_decode<<<((long long)NPRED * 16 + TB - 1) / TB, TB>>>(pred, out);
}

// round 3
// speedup vs baseline: 1.3045x; 1.1330x over previous
#include <cuda_runtime.h>

#define N_NODES 50000
#define HID     64
#define NE      800000
#define NPRED   100000
#define NL      2
#define BN_EPS  1e-5f

// ---------------- scratch ----------------------------------------------------
__device__ float g_dis[N_NODES];
__device__ float g_x  [N_NODES * HID];
__device__ float g_h  [N_NODES * HID];
__device__ float g_agg[N_NODES * HID];
__device__ float g_sums [HID];
__device__ float g_sumsq[HID];
__device__ float g_mu   [HID];
__device__ float g_scale[HID];
// CSR
__device__ int g_cnt [N_NODES];
__device__ int g_fill[N_NODES];
__device__ int g_off [N_NODES + 1];
__device__ int g_bsum[256];
__device__ int g_boff[256];
__device__ int g_src [NE];

// ---------------- f32x2 helpers ----------------------------------------------
__device__ __forceinline__ unsigned long long pack2(float v) {
    unsigned long long r;
    asm("mov.b64 %0, {%1, %1};" : "=l"(r) : "f"(v));
    return r;
}
__device__ __forceinline__ void ffma2(unsigned long long& d,
                                      unsigned long long a, unsigned long long b) {
    asm("fma.rn.f32x2 %0, %1, %2, %0;" : "+l"(d) : "l"(a), "l"(b));
}

// ---------------- CSR build --------------------------------------------------
__global__ void k_zero() {
    int i = blockIdx.x * 256 + threadIdx.x;
    if (i < N_NODES) { g_cnt[i] = 0; g_fill[i] = 0; }
}
__global__ void k_count(const int* __restrict__ col) {
    int e = blockIdx.x * 256 + threadIdx.x;
    if (e < NE) atomicAdd(&g_cnt[col[e]], 1);
}
__global__ void k_scan1() {
    __shared__ int s[256];
    int tid = threadIdx.x;
    int i = blockIdx.x * 256 + tid;
    int v = (i < N_NODES) ? g_cnt[i] : 0;
    s[tid] = v; __syncthreads();
    for (int d = 1; d < 256; d <<= 1) {
        int t = (tid >= d) ? s[tid - d] : 0;
        __syncthreads(); s[tid] += t; __syncthreads();
    }
    if (i < N_NODES) g_off[i] = s[tid] - v;
    if (tid == 255) g_bsum[blockIdx.x] = s[255];
}
__global__ void k_scan2(int nblk) {
    __shared__ int s[256];
    int tid = threadIdx.x;
    int v = (tid < nblk) ? g_bsum[tid] : 0;
    s[tid] = v; __syncthreads();
    for (int d = 1; d < 256; d <<= 1) {
        int t = (tid >= d) ? s[tid - d] : 0;
        __syncthreads(); s[tid] += t; __syncthreads();
    }
    g_boff[tid] = s[tid] - v;
}
__global__ void k_scan3() {
    int i = blockIdx.x * 256 + threadIdx.x;
    if (i < N_NODES) {
        g_off[i] += g_boff[i >> 8];
        g_dis[i] = rsqrtf((float)g_cnt[i] + 1.0f);   // +1 self-loop
    }
    if (i == 0) g_off[N_NODES] = NE;
}
__global__ void k_fill(const int* __restrict__ row, const int* __restrict__ col) {
    int e = blockIdx.x * 256 + threadIdx.x;
    if (e >= NE) return;
    int c = col[e];
    int p = atomicAdd(&g_fill[c], 1);
    g_src[g_off[c] + p] = row[e];
}

// ---------------- input projection: x = [id|n2v] @ Wp + bp -------------------
// 2 threads per row, each computes 32 outputs (16 f32x2 accumulators).
__global__ __launch_bounds__(256) void k_proj(const float* __restrict__ id_emb,
                                              const float* __restrict__ n2v,
                                              const float* __restrict__ W,  // [128,64]
                                              const float* __restrict__ b) {
    __shared__ ulonglong2 sW[128 * 16];   // 32 KB
    int tid = threadIdx.x;
    for (int i = tid; i < 128 * 16; i += 256) sW[i] = ((const ulonglong2*)W)[i];
    __syncthreads();

    int row  = blockIdx.x * 128 + (tid >> 1);
    int half = tid & 1;
    if (row >= N_NODES) return;

    unsigned long long acc[16];
    const unsigned long long* b2 = (const unsigned long long*)b;
    #pragma unroll
    for (int p = 0; p < 16; p++) acc[p] = b2[half * 16 + p];

    const float4* xa = (const float4*)(id_emb + (size_t)row * 64);
    const float4* xb = (const float4*)(n2v    + (size_t)row * 64);

    #pragma unroll 4
    for (int k4 = 0; k4 < 32; k4++) {
        float4 xv4 = (k4 < 16) ? xa[k4] : xb[k4 - 16];
        float xs[4] = {xv4.x, xv4.y, xv4.z, xv4.w};
        #pragma unroll
        for (int j = 0; j < 4; j++) {
            unsigned long long xp = pack2(xs[j]);
            const ulonglong2* wr = &sW[(k4 * 4 + j) * 16 + half * 8];
            #pragma unroll
            for (int q = 0; q < 8; q++) {
                ulonglong2 w = wr[q];
                ffma2(acc[2 * q],     xp, w.x);
                ffma2(acc[2 * q + 1], xp, w.y);
            }
        }
    }
    ulonglong2* xo = (ulonglong2*)(g_x + (size_t)row * 64) + half * 8;
    #pragma unroll
    for (int q = 0; q < 8; q++) {
        ulonglong2 o; o.x = acc[2 * q]; o.y = acc[2 * q + 1];
        xo[q] = o;
    }
}

// ---------------- per-layer GEMM (+ fused prev-layer BN apply) ---------------
// phase A: x += relu(BN(agg)) in-place (if apply_prev); phase B: h = x @ W.
__global__ __launch_bounds__(256) void k_layer_gemm(const float* __restrict__ W, // [64,64]
                                                    const float* __restrict__ beta_prev,
                                                    int apply_prev) {
    __shared__ ulonglong2 sW[64 * 16];    // 16 KB
    int tid = threadIdx.x;
    for (int i = tid; i < 64 * 16; i += 256) sW[i] = ((const ulonglong2*)W)[i];

    if (blockIdx.x == 0 && tid < 16) {
        ((float4*)g_sums)[tid]  = make_float4(0.f, 0.f, 0.f, 0.f);
        ((float4*)g_sumsq)[tid] = make_float4(0.f, 0.f, 0.f, 0.f);
    }

    int base = blockIdx.x * 128;
    if (apply_prev) {
        __syncthreads();   // sW done (also covers stats zero ordering w/in blk0)
        for (int i = tid; i < 128 * 16; i += 256) {
            int r = base + (i >> 4);
            if (r >= N_NODES) break;
            int q = i & 15;
            float4 a  = ((const float4*)g_agg)[r * 16 + q];
            float4 x  = ((float4*)g_x)[r * 16 + q];
            float4 mu = ((const float4*)g_mu)[q];
            float4 sc = ((const float4*)g_scale)[q];
            float4 bt = ((const float4*)beta_prev)[q];
            x.x += fmaxf((a.x - mu.x) * sc.x + bt.x, 0.0f);
            x.y += fmaxf((a.y - mu.y) * sc.y + bt.y, 0.0f);
            x.z += fmaxf((a.z - mu.z) * sc.z + bt.z, 0.0f);
            x.w += fmaxf((a.w - mu.w) * sc.w + bt.w, 0.0f);
            ((float4*)g_x)[r * 16 + q] = x;
        }
    }
    __syncthreads();

    int row  = base + (tid >> 1);
    int half = tid & 1;
    if (row >= N_NODES) return;

    unsigned long long acc[16];
    #pragma unroll
    for (int p = 0; p < 16; p++) acc[p] = 0ull;

    const float4* xg = (const float4*)(g_x + (size_t)row * 64);
    #pragma unroll 4
    for (int k4 = 0; k4 < 16; k4++) {
        float4 xv4 = xg[k4];
        float xs[4] = {xv4.x, xv4.y, xv4.z, xv4.w};
        #pragma unroll
        for (int j = 0; j < 4; j++) {
            unsigned long long xp = pack2(xs[j]);
            const ulonglong2* wr = &sW[(k4 * 4 + j) * 16 + half * 8];
            #pragma unroll
            for (int q = 0; q < 8; q++) {
                ulonglong2 w = wr[q];
                ffma2(acc[2 * q],     xp, w.x);
                ffma2(acc[2 * q + 1], xp, w.y);
            }
        }
    }
    ulonglong2* ho = (ulonglong2*)(g_h + (size_t)row * 64) + half * 8;
    #pragma unroll
    for (int q = 0; q < 8; q++) {
        ulonglong2 o; o.x = acc[2 * q]; o.y = acc[2 * q + 1];
        ho[q] = o;
    }
}

// ---------------- CSR gather: agg[i] = sum_e norm*h[src] + h[i]/deg + bias ---
// 16 lanes per node; also accumulates BN sum/sumsq per channel (fused stats).
__global__ __launch_bounds__(256) void k_gather(const float* __restrict__ convb) {
    int gid  = blockIdx.x * 256 + threadIdx.x;
    int node = gid >> 4;
    int l    = gid & 15;

    float d  = g_dis[node];
    float d2 = d * d;
    float4 b4 = ((const float4*)convb)[l];
    float4 h0 = ((const float4*)g_h)[node * 16 + l];
    float4 acc = make_float4(h0.x * d2 + b4.x, h0.y * d2 + b4.y,
                             h0.z * d2 + b4.z, h0.w * d2 + b4.w);

    int beg = g_off[node], end = g_off[node + 1];
    for (int j = beg; j < end; j++) {
        int r   = g_src[j];
        float w = d * g_dis[r];
        float4 v = ((const float4*)g_h)[r * 16 + l];
        acc.x += w * v.x; acc.y += w * v.y;
        acc.z += w * v.z; acc.w += w * v.w;
    }
    ((float4*)g_agg)[node * 16 + l] = acc;

    // ---- fused BN stats ----
    float4 sq = make_float4(acc.x * acc.x, acc.y * acc.y,
                            acc.z * acc.z, acc.w * acc.w);
    acc.x += __shfl_xor_sync(0xffffffffu, acc.x, 16);
    acc.y += __shfl_xor_sync(0xffffffffu, acc.y, 16);
    acc.z += __shfl_xor_sync(0xffffffffu, acc.z, 16);
    acc.w += __shfl_xor_sync(0xffffffffu, acc.w, 16);
    sq.x  += __shfl_xor_sync(0xffffffffu, sq.x, 16);
    sq.y  += __shfl_xor_sync(0xffffffffu, sq.y, 16);
    sq.z  += __shfl_xor_sync(0xffffffffu, sq.z, 16);
    sq.w  += __shfl_xor_sync(0xffffffffu, sq.w, 16);

    __shared__ float4 ss[8][16], sg[8][16];
    int wid = threadIdx.x >> 5, lane = threadIdx.x & 31;
    if (lane < 16) { ss[wid][lane] = acc; sg[wid][lane] = sq; }
    __syncthreads();
    if (threadIdx.x < 16) {
        float4 S = make_float4(0.f, 0.f, 0.f, 0.f);
        float4 Q = make_float4(0.f, 0.f, 0.f, 0.f);
        #pragma unroll
        for (int t = 0; t < 8; t++) {
            float4 a = ss[t][threadIdx.x], q = sg[t][threadIdx.x];
            S.x += a.x; S.y += a.y; S.z += a.z; S.w += a.w;
            Q.x += q.x; Q.y += q.y; Q.z += q.z; Q.w += q.w;
        }
        atomicAdd(((float4*)g_sums)  + threadIdx.x, S);
        atomicAdd(((float4*)g_sumsq) + threadIdx.x, Q);
    }
}

__global__ void k_bnfinal(const float* __restrict__ gamma) {
    int c = threadIdx.x;
    const float inv_n = 1.0f / (float)N_NODES;
    float mu  = g_sums[c] * inv_n;
    float var = g_sumsq[c] * inv_n - mu * mu;
    g_mu[c]    = mu;
    g_scale[c] = rsqrtf(var + BN_EPS) * gamma[c];
}

// ---------------- final x = x + relu(BN(agg)) --------------------------------
__global__ void k_apply(const float* __restrict__ beta) {
    int idx = blockIdx.x * 256 + threadIdx.x;
    if (idx >= N_NODES * 16) return;
    int cq = idx & 15;
    float4 a  = ((const float4*)g_agg)[idx];
    float4 x  = ((float4*)g_x)[idx];
    float4 mu = ((const float4*)g_mu)[cq];
    float4 sc = ((const float4*)g_scale)[cq];
    float4 bt = ((const float4*)beta)[cq];
    x.x += fmaxf((a.x - mu.x) * sc.x + bt.x, 0.0f);
    x.y += fmaxf((a.y - mu.y) * sc.y + bt.y, 0.0f);
    x.z += fmaxf((a.z - mu.z) * sc.z + bt.z, 0.0f);
    x.w += fmaxf((a.w - mu.w) * sc.w + bt.w, 0.0f);
    ((float4*)g_x)[idx] = x;
}

// ---------------- link decoder ----------------------------------------------
__global__ void k_decode(const int* __restrict__ pred, float* __restrict__ out) {
    int gid = blockIdx.x * 256 + threadIdx.x;
    int p = gid >> 4;
    int l = gid & 15;
    if (p >= NPRED) return;
    int a = pred[2 * p];
    int b = pred[2 * p + 1];
    float4 va = ((const float4*)g_x)[a * 16 + l];
    float4 vb = ((const float4*)g_x)[b * 16 + l];
    float s = va.x * vb.x + va.y * vb.y + va.z * vb.z + va.w * vb.w;
    s += __shfl_xor_sync(0xffffffffu, s, 8);
    s += __shfl_xor_sync(0xffffffffu, s, 4);
    s += __shfl_xor_sync(0xffffffffu, s, 2);
    s += __shfl_xor_sync(0xffffffffu, s, 1);
    if (l == 0) out[p] = s;
}

// ---------------- launch ------------------------------------------------------
extern "C" void kernel_launch(void* const* d_in, const int* in_sizes, int n_in,
                              void* d_out, int out_size) {
    const int*   edge    = (const int*)  d_in[0];   // [2, NE]
    const int*   pred    = (const int*)  d_in[1];   // [NPRED, 2]
    const float* id_emb  = (const float*)d_in[2];   // [N, 64]
    const float* n2v     = (const float*)d_in[3];   // [N, 64]
    const float* proj_w  = (const float*)d_in[4];   // [128, 64]
    const float* proj_b  = (const float*)d_in[5];   // [64]
    const float* conv_w  = (const float*)d_in[6];   // [2, 64, 64]
    const float* conv_b  = (const float*)d_in[7];   // [2, 64]
    const float* gamma   = (const float*)d_in[8];   // [2, 64]
    const float* beta    = (const float*)d_in[9];   // [2, 64]
    float* out = (float*)d_out;

    const int NB_N = (N_NODES + 255) / 256;     // 196
    const int NB_E = (NE + 255) / 256;          // 3125
    const int NB_R = (N_NODES + 127) / 128;     // 391

    // CSR build
    k_zero <<<NB_N, 256>>>();
    k_count<<<NB_E, 256>>>(edge + NE);
    k_scan1<<<NB_N, 256>>>();
    k_scan2<<<1, 256>>>(NB_N);
    k_scan3<<<NB_N, 256>>>();
    k_fill <<<NB_E, 256>>>(edge, edge + NE);

    k_proj<<<NB_R, 256>>>(id_emb, n2v, proj_w, proj_b);

    for (int l = 0; l < NL; l++) {
        k_layer_gemm<<<NB_R, 256>>>(conv_w + l * HID * HID,
                                    (l > 0) ? (beta + (l - 1) * HID) : nullptr,
                                    (l > 0) ? 1 : 0);
        k_gather  <<<N_NODES * 16 / 256, 256>>>(conv_b + l * HID);
        k_bnfinal <<<1, 64>>>(gamma + l * HID);
    }

    k_apply <<<N_NODES * 16 / 256, 256>>>(beta + (NL - 1) * HID);
    k_decode<<<NPRED * 16 / 256, 256>>>(pred, out);
}

// round 4
// speedup vs baseline: 1.3600x; 1.0425x over previous
#include <cuda_runtime.h>

#define N_NODES 50000
#define HID     64
#define NE      800000
#define NPRED   100000
#define NL      2
#define BN_EPS  1e-5f

// ---------------- zeroed blob (single memsetAsync per call) ------------------
// ints [0,50000)            : g_cnt (in-degree histogram)
// ints [50000,50512)        : 256 x u64 lookback descriptors ((flag<<32)|value)
// ints [50512,50768)        : BN sums: 2 layers x (64 sum + 64 sumsq) floats
#define ZB_INTS  (N_NODES + 512 + 256)
__device__ __align__(256) int g_zb[ZB_INTS];

#define P_CNT   (g_zb)
#define P_DESC  ((volatile unsigned long long*)(g_zb + N_NODES))
#define P_SUMS  ((float*)(g_zb + N_NODES + 512))     // [layer*128 + c]=sum, +64=sumsq

// ---------------- other scratch ----------------------------------------------
__device__ float g_dis[N_NODES];
__device__ float g_x  [N_NODES * HID];
__device__ float g_agg[N_NODES * HID];
__device__ int   g_fill[N_NODES];
__device__ int   g_off [N_NODES + 1];
__device__ int2  g_pair[NE];              // (src, __float_as_int(norm))

// ---------------- f32x2 helpers ----------------------------------------------
__device__ __forceinline__ unsigned long long pack2(float v) {
    unsigned long long r;
    asm("mov.b64 %0, {%1, %1};" : "=l"(r) : "f"(v));
    return r;
}
__device__ __forceinline__ void ffma2(unsigned long long& d,
                                      unsigned long long a, unsigned long long b) {
    asm("fma.rn.f32x2 %0, %1, %2, %0;" : "+l"(d) : "l"(a), "l"(b));
}

// ---------------- degree count -----------------------------------------------
__global__ void k_count(const int* __restrict__ col) {
    int e = blockIdx.x * 256 + threadIdx.x;
    if (e < NE) atomicAdd(&P_CNT[e < NE ? col[e] : 0], 1);
}

// ---------------- single-kernel exclusive scan (decoupled lookback) ----------
__global__ void k_scan() {
    __shared__ int s[256];
    __shared__ int s_prefix;
    int tid = threadIdx.x, b = blockIdx.x;
    int i = b * 256 + tid;
    int v = (i < N_NODES) ? P_CNT[i] : 0;
    s[tid] = v; __syncthreads();
    #pragma unroll
    for (int d = 1; d < 256; d <<= 1) {
        int t = (tid >= d) ? s[tid - d] : 0;
        __syncthreads(); s[tid] += t; __syncthreads();
    }
    if (tid == 0) {
        int total = s[255];
        if (b == 0) {
            P_DESC[0] = (2ull << 32) | (unsigned)total;   // inclusive ready
            s_prefix = 0;
        } else {
            P_DESC[b] = (1ull << 32) | (unsigned)total;   // aggregate ready
            int pre = 0;
            for (int j = b - 1; j >= 0; ) {
                unsigned long long w;
                do { w = P_DESC[j]; } while ((w >> 32) == 0ull);
                pre += (int)(unsigned)w;
                if ((w >> 32) == 2ull) break;
                j--;
            }
            P_DESC[b] = (2ull << 32) | (unsigned)(pre + total);
            s_prefix = pre;
        }
    }
    __syncthreads();
    if (i < N_NODES) {
        g_off[i]  = s_prefix + s[tid] - v;          // exclusive prefix
        g_dis[i]  = rsqrtf((float)v + 1.0f);        // +1 self-loop
        g_fill[i] = 0;
    }
    if (i == 0) g_off[N_NODES] = NE;
}

// ---------------- CSR fill with precomputed edge weight ----------------------
__global__ void k_fill(const int* __restrict__ row, const int* __restrict__ col) {
    int e = blockIdx.x * 256 + threadIdx.x;
    if (e >= NE) return;
    int r = row[e], c = col[e];
    int p = atomicAdd(&g_fill[c], 1);
    float w = g_dis[r] * g_dis[c];
    g_pair[g_off[c] + p] = make_int2(r, __float_as_int(w));
}

// ---------------- input projection: x = [id|n2v] @ Wp + bp -------------------
__global__ __launch_bounds__(256) void k_proj(const float* __restrict__ id_emb,
                                              const float* __restrict__ n2v,
                                              const float* __restrict__ W,  // [128,64]
                                              const float* __restrict__ b) {
    __shared__ ulonglong2 sW[128 * 16];   // 32 KB
    int tid = threadIdx.x;
    for (int i = tid; i < 128 * 16; i += 256) sW[i] = ((const ulonglong2*)W)[i];
    __syncthreads();

    int row  = blockIdx.x * 128 + (tid >> 1);
    int half = tid & 1;
    if (row >= N_NODES) return;

    unsigned long long acc[16];
    const unsigned long long* b2 = (const unsigned long long*)b;
    #pragma unroll
    for (int p = 0; p < 16; p++) acc[p] = b2[half * 16 + p];

    const float4* xa = (const float4*)(id_emb + (size_t)row * 64);
    const float4* xb = (const float4*)(n2v    + (size_t)row * 64);

    #pragma unroll 4
    for (int k4 = 0; k4 < 32; k4++) {
        float4 xv4 = (k4 < 16) ? xa[k4] : xb[k4 - 16];
        float xs[4] = {xv4.x, xv4.y, xv4.z, xv4.w};
        #pragma unroll
        for (int j = 0; j < 4; j++) {
            unsigned long long xp = pack2(xs[j]);
            const ulonglong2* wr = &sW[(k4 * 4 + j) * 16 + half * 8];
            #pragma unroll
            for (int q = 0; q < 8; q++) {
                ulonglong2 w = wr[q];
                ffma2(acc[2 * q],     xp, w.x);
                ffma2(acc[2 * q + 1], xp, w.y);
            }
        }
    }
    ulonglong2* xo = (ulonglong2*)(g_x + (size_t)row * 64) + half * 8;
    #pragma unroll
    for (int q = 0; q < 8; q++) {
        ulonglong2 o; o.x = acc[2 * q]; o.y = acc[2 * q + 1];
        xo[q] = o;
    }
}

// ---------------- fused gather(x) + GEMM + BN stats --------------------------
// agg = (A_hat x) W + b ; per-channel sum/sumsq accumulated into P_SUMS[layer].
// Block = 256 threads = 16 nodes x 16 lanes.
#define SXP 68   // padded row stride (floats), 16B-aligned, bank-skewed
__global__ __launch_bounds__(256) void k_gg(const float* __restrict__ W,     // [64,64]
                                            const float* __restrict__ convb,
                                            int layer) {
    __shared__ ulonglong2 sW[64 * 16];    // 16 KB
    __shared__ float sX[16 * SXP];        // 4.25 KB
    int tid = threadIdx.x;
    for (int i = tid; i < 64 * 16; i += 256) sW[i] = ((const ulonglong2*)W)[i];

    int ln   = tid >> 4;                  // local node 0..15
    int l    = tid & 15;                  // lane within node
    int node = blockIdx.x * 16 + ln;
    unsigned m = (tid & 16) ? 0xFFFF0000u : 0x0000FFFFu;   // half-warp mask

    // ---- gather phase: acc = d^2 * x[node] + sum_e w_e * x[src_e] ----
    float d  = g_dis[node];
    float d2 = d * d;
    float4 xs = ((const float4*)g_x)[node * 16 + l];
    float4 acc = make_float4(xs.x * d2, xs.y * d2, xs.z * d2, xs.w * d2);

    int beg = g_off[node], end = g_off[node + 1];
    for (int t = beg; t < end; t += 16) {
        int j = t + l;
        int2 pr = (j < end) ? g_pair[j] : make_int2(0, 0);
        int kn = end - t; if (kn > 16) kn = 16;
        for (int k = 0; k < kn; k++) {
            int   r = __shfl_sync(m, pr.x, k, 16);
            float w = __int_as_float(__shfl_sync(m, pr.y, k, 16));
            float4 v = ((const float4*)g_x)[r * 16 + l];
            acc.x += w * v.x; acc.y += w * v.y;
            acc.z += w * v.z; acc.w += w * v.w;
        }
    }
    *(float4*)(sX + ln * SXP + l * 4) = acc;
    __syncthreads();

    // ---- GEMM phase: out[ln][q*4..] = sum_k sX[ln][k] * W[k][q*4..] ----
    unsigned long long a0 = 0ull, a1 = 0ull;
    const float* xrow = sX + ln * SXP;
    #pragma unroll 8
    for (int k = 0; k < 64; k++) {
        unsigned long long xp = pack2(xrow[k]);
        ulonglong2 w = sW[k * 16 + l];
        ffma2(a0, xp, w.x);
        ffma2(a1, xp, w.y);
    }
    float4 b4 = ((const float4*)convb)[l];
    float2 lo, hi;
    asm("mov.b64 {%0, %1}, %2;" : "=f"(lo.x), "=f"(lo.y) : "l"(a0));
    asm("mov.b64 {%0, %1}, %2;" : "=f"(hi.x), "=f"(hi.y) : "l"(a1));
    float4 o = make_float4(lo.x + b4.x, lo.y + b4.y, hi.x + b4.z, hi.y + b4.w);
    ((float4*)g_agg)[node * 16 + l] = o;

    // ---- BN stats ----
    float4 sq = make_float4(o.x * o.x, o.y * o.y, o.z * o.z, o.w * o.w);
    o.x  += __shfl_xor_sync(0xffffffffu, o.x, 16);
    o.y  += __shfl_xor_sync(0xffffffffu, o.y, 16);
    o.z  += __shfl_xor_sync(0xffffffffu, o.z, 16);
    o.w  += __shfl_xor_sync(0xffffffffu, o.w, 16);
    sq.x += __shfl_xor_sync(0xffffffffu, sq.x, 16);
    sq.y += __shfl_xor_sync(0xffffffffu, sq.y, 16);
    sq.z += __shfl_xor_sync(0xffffffffu, sq.z, 16);
    sq.w += __shfl_xor_sync(0xffffffffu, sq.w, 16);

    __shared__ float4 ss[8][16], sg[8][16];
    int wid = tid >> 5, lane = tid & 31;
    if (lane < 16) { ss[wid][lane] = o; sg[wid][lane] = sq; }
    __syncthreads();
    if (tid < 16) {
        float4 S = make_float4(0.f, 0.f, 0.f, 0.f);
        float4 Q = make_float4(0.f, 0.f, 0.f, 0.f);
        #pragma unroll
        for (int t = 0; t < 8; t++) {
            float4 a = ss[t][tid], q = sg[t][tid];
            S.x += a.x; S.y += a.y; S.z += a.z; S.w += a.w;
            Q.x += q.x; Q.y += q.y; Q.z += q.z; Q.w += q.w;
        }
        float* base = P_SUMS + layer * 128;
        atomicAdd(((float4*)base) + tid,       S);
        atomicAdd(((float4*)(base + 64)) + tid, Q);
    }
}

// ---------------- x += relu(BN(agg)) (BN params computed in-block) -----------
__global__ __launch_bounds__(256) void k_apply(const float* __restrict__ gamma,
                                               const float* __restrict__ beta,
                                               int layer) {
    __shared__ float smu[64], ssc[64];
    int tid = threadIdx.x;
    if (tid < 64) {
        const float* base = P_SUMS + layer * 128;
        const float inv_n = 1.0f / (float)N_NODES;
        float mu  = base[tid] * inv_n;
        float var = base[64 + tid] * inv_n - mu * mu;
        smu[tid] = mu;
        ssc[tid] = rsqrtf(var + BN_EPS) * gamma[tid];
    }
    __syncthreads();
    int idx = blockIdx.x * 256 + tid;
    int cq  = idx & 15;
    float4 a  = ((const float4*)g_agg)[idx];
    float4 x  = ((float4*)g_x)[idx];
    float4 mu = ((const float4*)smu)[cq];
    float4 sc = ((const float4*)ssc)[cq];
    float4 bt = ((const float4*)beta)[cq];
    x.x += fmaxf((a.x - mu.x) * sc.x + bt.x, 0.0f);
    x.y += fmaxf((a.y - mu.y) * sc.y + bt.y, 0.0f);
    x.z += fmaxf((a.z - mu.z) * sc.z + bt.z, 0.0f);
    x.w += fmaxf((a.w - mu.w) * sc.w + bt.w, 0.0f);
    ((float4*)g_x)[idx] = x;
}

// ---------------- decoder with fused final BN apply --------------------------
__global__ __launch_bounds__(256) void k_decode(const int* __restrict__ pred,
                                                const float* __restrict__ gamma,
                                                const float* __restrict__ beta,
                                                float* __restrict__ out,
                                                int layer) {
    __shared__ float smu[64], ssc[64], sbt[64];
    int tid = threadIdx.x;
    if (tid < 64) {
        const float* base = P_SUMS + layer * 128;
        const float inv_n = 1.0f / (float)N_NODES;
        float mu  = base[tid] * inv_n;
        float var = base[64 + tid] * inv_n - mu * mu;
        smu[tid] = mu;
        ssc[tid] = rsqrtf(var + BN_EPS) * gamma[tid];
        sbt[tid] = beta[tid];
    }
    __syncthreads();
    int gid = blockIdx.x * 256 + tid;
    int p = gid >> 4;
    int l = gid & 15;
    int a = pred[2 * p];
    int b = pred[2 * p + 1];
    float4 mu = ((const float4*)smu)[l];
    float4 sc = ((const float4*)ssc)[l];
    float4 bt = ((const float4*)sbt)[l];

    float4 xa = ((const float4*)g_x)[a * 16 + l];
    float4 ga = ((const float4*)g_agg)[a * 16 + l];
    float4 za = make_float4(
        xa.x + fmaxf((ga.x - mu.x) * sc.x + bt.x, 0.0f),
        xa.y + fmaxf((ga.y - mu.y) * sc.y + bt.y, 0.0f),
        xa.z + fmaxf((ga.z - mu.z) * sc.z + bt.z, 0.0f),
        xa.w + fmaxf((ga.w - mu.w) * sc.w + bt.w, 0.0f));
    float4 xb = ((const float4*)g_x)[b * 16 + l];
    float4 gb = ((const float4*)g_agg)[b * 16 + l];
    float4 zb = make_float4(
        xb.x + fmaxf((gb.x - mu.x) * sc.x + bt.x, 0.0f),
        xb.y + fmaxf((gb.y - mu.y) * sc.y + bt.y, 0.0f),
        xb.z + fmaxf((gb.z - mu.z) * sc.z + bt.z, 0.0f),
        xb.w + fmaxf((gb.w - mu.w) * sc.w + bt.w, 0.0f));

    float s = za.x * zb.x + za.y * zb.y + za.z * zb.z + za.w * zb.w;
    s += __shfl_xor_sync(0xffffffffu, s, 8);
    s += __shfl_xor_sync(0xffffffffu, s, 4);
    s += __shfl_xor_sync(0xffffffffu, s, 2);
    s += __shfl_xor_sync(0xffffffffu, s, 1);
    if (l == 0) out[p] = s;
}

// ---------------- launch ------------------------------------------------------
extern "C" void kernel_launch(void* const* d_in, const int* in_sizes, int n_in,
                              void* d_out, int out_size) {
    const int*   edge    = (const int*)  d_in[0];   // [2, NE]
    const int*   pred    = (const int*)  d_in[1];   // [NPRED, 2]
    const float* id_emb  = (const float*)d_in[2];   // [N, 64]
    const float* n2v     = (const float*)d_in[3];   // [N, 64]
    const float* proj_w  = (const float*)d_in[4];   // [128, 64]
    const float* proj_b  = (const float*)d_in[5];   // [64]
    const float* conv_w  = (const float*)d_in[6];   // [2, 64, 64]
    const float* conv_b  = (const float*)d_in[7];   // [2, 64]
    const float* gamma   = (const float*)d_in[8];   // [2, 64]
    const float* beta    = (const float*)d_in[9];   // [2, 64]
    float* out = (float*)d_out;

    void* zp = nullptr;
    cudaGetSymbolAddress(&zp, g_zb);
    cudaMemsetAsync(zp, 0, ZB_INTS * sizeof(int));

    const int NB_E = (NE + 255) / 256;          // 3125
    const int NB_S = (N_NODES + 255) / 256;     // 196

    k_count<<<NB_E, 256>>>(edge + NE);
    k_scan <<<NB_S, 256>>>();
    k_fill <<<NB_E, 256>>>(edge, edge + NE);
    k_proj <<<(N_NODES + 127) / 128, 256>>>(id_emb, n2v, proj_w, proj_b);

    k_gg    <<<N_NODES / 16, 256>>>(conv_w,                 conv_b,       0);
    k_apply <<<N_NODES * 16 / 256, 256>>>(gamma,            beta,         0);
    k_gg    <<<N_NODES / 16, 256>>>(conv_w + HID * HID,     conv_b + HID, 1);
    k_decode<<<NPRED * 16 / 256, 256>>>(pred, gamma + HID,  beta + HID, out, 1);
}

// round 5
// speedup vs baseline: 1.4933x; 1.0981x over previous
#include <cuda_runtime.h>

#define N_NODES 50000
#define HID     64
#define NE      800000
#define NPRED   100000
#define NL      2
#define BN_EPS  1e-5f

// ---------------- zeroed blob (single memsetAsync per call) ------------------
// ints [0,50000)     : g_cnt (in-degree histogram)
// ints [50000,50512) : 256 x u64 lookback descriptors ((flag<<32)|value)
// ints [50512,50768) : BN sums: 2 layers x (64 sum + 64 sumsq) floats
#define ZB_INTS  (N_NODES + 512 + 256)
__device__ __align__(256) int g_zb[ZB_INTS];

#define P_CNT   (g_zb)
#define P_DESC  ((volatile unsigned long long*)(g_zb + N_NODES))
#define P_SUMS  ((float*)(g_zb + N_NODES + 512))   // [layer*128 + c]=sum, +64=sumsq

// ---------------- other scratch ----------------------------------------------
__device__ float g_dis[N_NODES];
__device__ float g_x  [N_NODES * HID];
__device__ float g_agg[N_NODES * HID];
__device__ int   g_fill[N_NODES];
__device__ int   g_off [N_NODES + 1];
__device__ int2  g_pair[NE];              // (src, __float_as_int(norm))

// ---------------- f32x2 helper -----------------------------------------------
__device__ __forceinline__ void ffma2(unsigned long long& d,
                                      unsigned long long a, unsigned long long b) {
    asm("fma.rn.f32x2 %0, %1, %2, %0;" : "+l"(d) : "l"(a), "l"(b));
}

// ---------------- degree count -----------------------------------------------
__global__ void k_count(const int* __restrict__ col) {
    int e = blockIdx.x * 256 + threadIdx.x;
    if (e < NE) atomicAdd(&P_CNT[col[e]], 1);
}

// ---------------- single-kernel exclusive scan (decoupled lookback) ----------
__global__ void k_scan() {
    __shared__ int s[256];
    __shared__ int s_prefix;
    int tid = threadIdx.x, b = blockIdx.x;
    int i = b * 256 + tid;
    int v = (i < N_NODES) ? P_CNT[i] : 0;
    s[tid] = v; __syncthreads();
    #pragma unroll
    for (int d = 1; d < 256; d <<= 1) {
        int t = (tid >= d) ? s[tid - d] : 0;
        __syncthreads(); s[tid] += t; __syncthreads();
    }
    if (tid == 0) {
        int total = s[255];
        if (b == 0) {
            P_DESC[0] = (2ull << 32) | (unsigned)total;
            s_prefix = 0;
        } else {
            P_DESC[b] = (1ull << 32) | (unsigned)total;
            int pre = 0;
            for (int j = b - 1; j >= 0; ) {
                unsigned long long w;
                do { w = P_DESC[j]; } while ((w >> 32) == 0ull);
                pre += (int)(unsigned)w;
                if ((w >> 32) == 2ull) break;
                j--;
            }
            P_DESC[b] = (2ull << 32) | (unsigned)(pre + total);
            s_prefix = pre;
        }
    }
    __syncthreads();
    if (i < N_NODES) {
        g_off[i]  = s_prefix + s[tid] - v;
        g_dis[i]  = rsqrtf((float)v + 1.0f);      // +1 self-loop
        g_fill[i] = 0;
    }
    if (i == 0) g_off[N_NODES] = NE;
}

// ---------------- CSR fill with precomputed edge weight ----------------------
__global__ void k_fill(const int* __restrict__ row, const int* __restrict__ col) {
    int e = blockIdx.x * 256 + threadIdx.x;
    if (e >= NE) return;
    int r = row[e], c = col[e];
    int p = atomicAdd(&g_fill[c], 1);
    float w = g_dis[r] * g_dis[c];
    g_pair[g_off[c] + p] = make_int2(r, __float_as_int(w));
}

// ---------------- input projection: x = [id|n2v] @ Wp + bp -------------------
// Thread = (row-pair, col-half): 2 rows x 32 outputs. W LDS amortized over 2 rows.
__global__ __launch_bounds__(256) void k_proj(const float* __restrict__ id_emb,
                                              const float* __restrict__ n2v,
                                              const float* __restrict__ W,  // [128,64]
                                              const float* __restrict__ b) {
    __shared__ float4 sW[128 * 16];   // 32 KB
    int tid = threadIdx.x;
    for (int i = tid; i < 128 * 16; i += 256) sW[i] = ((const float4*)W)[i];
    __syncthreads();

    int pair = tid >> 1;
    int half = tid & 1;
    int r0 = blockIdx.x * 256 + pair * 2;
    int r1 = r0 + 1;
    bool v0 = r0 < N_NODES, v1 = r1 < N_NODES;
    if (!v0) return;

    float4 acc0[8], acc1[8];
    const float4* b4 = ((const float4*)b) + half * 8;
    #pragma unroll
    for (int q = 0; q < 8; q++) { acc0[q] = b4[q]; acc1[q] = b4[q]; }

    const float4* xa0 = (const float4*)(id_emb + (size_t)r0 * 64);
    const float4* xb0 = (const float4*)(n2v    + (size_t)r0 * 64);
    const float4* xa1 = (const float4*)(id_emb + (size_t)r1 * 64);
    const float4* xb1 = (const float4*)(n2v    + (size_t)r1 * 64);

    #pragma unroll 2
    for (int k4 = 0; k4 < 32; k4++) {
        float4 xv0 = (k4 < 16) ? xa0[k4] : xb0[k4 - 16];
        float4 xv1 = v1 ? ((k4 < 16) ? xa1[k4] : xb1[k4 - 16])
                        : make_float4(0.f, 0.f, 0.f, 0.f);
        float xs0[4] = {xv0.x, xv0.y, xv0.z, xv0.w};
        float xs1[4] = {xv1.x, xv1.y, xv1.z, xv1.w};
        #pragma unroll
        for (int j = 0; j < 4; j++) {
            float x0 = xs0[j], x1 = xs1[j];
            const float4* wr = &sW[(k4 * 4 + j) * 16 + half * 8];
            #pragma unroll
            for (int q = 0; q < 8; q++) {
                float4 w = wr[q];
                acc0[q].x += x0 * w.x; acc0[q].y += x0 * w.y;
                acc0[q].z += x0 * w.z; acc0[q].w += x0 * w.w;
                acc1[q].x += x1 * w.x; acc1[q].y += x1 * w.y;
                acc1[q].z += x1 * w.z; acc1[q].w += x1 * w.w;
            }
        }
    }
    float4* o0 = (float4*)(g_x + (size_t)r0 * 64) + half * 8;
    #pragma unroll
    for (int q = 0; q < 8; q++) o0[q] = acc0[q];
    if (v1) {
        float4* o1 = (float4*)(g_x + (size_t)r1 * 64) + half * 8;
        #pragma unroll
        for (int q = 0; q < 8; q++) o1[q] = acc1[q];
    }
}

// ---------------- fused gather(x) + GEMM + BN stats --------------------------
// agg = (A_hat x) W + b. Block = 256 threads = 16 nodes.
// Gather: 16 lanes/node, writes x duplicated (v,v) into sXd.
// GEMM: warp w -> nodes {2w,2w+1}; lane l -> cols (2l,2l+1) via f32x2.
#define SXDP 66   // u64 row stride for sXd (64 + 2 pad)
__global__ __launch_bounds__(256) void k_gg(const float* __restrict__ W,     // [64,64]
                                            const float* __restrict__ convb,
                                            int layer) {
    __shared__ float sWs[64 * 64];                 // 16 KB, row-major copy
    __shared__ unsigned long long sXd[16 * SXDP];  // 8.25 KB, (x,x) pairs
    __shared__ float ss[8][64], sg[8][64];         // 4 KB
    int tid = threadIdx.x;
    for (int i = tid; i < 1024; i += 256) ((float4*)sWs)[i] = ((const float4*)W)[i];

    int ln   = tid >> 4;                  // local node 0..15
    int l16  = tid & 15;                  // gather lane
    int node = blockIdx.x * 16 + ln;
    unsigned m = (tid & 16) ? 0xFFFF0000u : 0x0000FFFFu;

    // ---- gather: acc = d^2 * x[node] + sum_e w_e * x[src_e] ----
    float d  = g_dis[node];
    float d2 = d * d;
    float4 xs = ((const float4*)g_x)[node * 16 + l16];
    float4 acc = make_float4(xs.x * d2, xs.y * d2, xs.z * d2, xs.w * d2);

    int beg = g_off[node], end = g_off[node + 1];
    for (int t = beg; t < end; t += 16) {
        int j = t + l16;
        int2 pr = (j < end) ? g_pair[j] : make_int2(0, 0);
        int kn = end - t; if (kn > 16) kn = 16;
        for (int k = 0; k < kn; k++) {
            int   r = __shfl_sync(m, pr.x, k, 16);
            float w = __int_as_float(__shfl_sync(m, pr.y, k, 16));
            float4 v = ((const float4*)g_x)[r * 16 + l16];
            acc.x += w * v.x; acc.y += w * v.y;
            acc.z += w * v.z; acc.w += w * v.w;
        }
    }
    // write duplicated pairs: channels 4*l16 .. 4*l16+3
    {
        float4* dst = (float4*)(sXd + ln * SXDP + l16 * 4);
        dst[0] = make_float4(acc.x, acc.x, acc.y, acc.y);
        dst[1] = make_float4(acc.z, acc.z, acc.w, acc.w);
    }
    __syncthreads();

    // ---- GEMM: 2 nodes per warp, lane l owns cols (2l, 2l+1) ----
    int w = tid >> 5, l = tid & 31;
    int n0 = blockIdx.x * 16 + 2 * w;
    const unsigned long long* xd0 = sXd + (2 * w)     * SXDP;
    const unsigned long long* xd1 = sXd + (2 * w + 1) * SXDP;
    unsigned long long a0 = 0ull, a1 = 0ull;
    #pragma unroll 8
    for (int k = 0; k < 64; k++) {
        unsigned long long wp = *(const unsigned long long*)(sWs + k * 64 + 2 * l);
        ffma2(a0, xd0[k], wp);
        ffma2(a1, xd1[k], wp);
    }
    float2 cb = *(const float2*)(convb + 2 * l);
    float2 f0, f1;
    asm("mov.b64 {%0, %1}, %2;" : "=f"(f0.x), "=f"(f0.y) : "l"(a0));
    asm("mov.b64 {%0, %1}, %2;" : "=f"(f1.x), "=f"(f1.y) : "l"(a1));
    f0.x += cb.x; f0.y += cb.y;
    f1.x += cb.x; f1.y += cb.y;
    ((float2*)g_agg)[n0 * 32 + l]       = f0;
    ((float2*)g_agg)[(n0 + 1) * 32 + l] = f1;

    // ---- BN stats: lane has cols (2l,2l+1) for 2 nodes ----
    ss[w][2 * l]     = f0.x + f1.x;
    ss[w][2 * l + 1] = f0.y + f1.y;
    sg[w][2 * l]     = f0.x * f0.x + f1.x * f1.x;
    sg[w][2 * l + 1] = f0.y * f0.y + f1.y * f1.y;
    __syncthreads();
    if (tid < 32) {
        int t = tid & 15;
        float4 S = make_float4(0.f, 0.f, 0.f, 0.f);
        float* arr0 = (tid < 16) ? &ss[0][0] : &sg[0][0];
        #pragma unroll
        for (int ww = 0; ww < 8; ww++) {
            float4 a = ((const float4*)(arr0 + ww * 64))[t];
            S.x += a.x; S.y += a.y; S.z += a.z; S.w += a.w;
        }
        float* base = P_SUMS + layer * 128 + ((tid < 16) ? 0 : 64);
        atomicAdd(((float4*)base) + t, S);
    }
}

// ---------------- x += relu(BN(agg)) (BN params computed in-block) -----------
__global__ __launch_bounds__(256) void k_apply(const float* __restrict__ gamma,
                                               const float* __restrict__ beta,
                                               int layer) {
    __shared__ float smu[64], ssc[64];
    int tid = threadIdx.x;
    if (tid < 64) {
        const float* base = P_SUMS + layer * 128;
        const float inv_n = 1.0f / (float)N_NODES;
        float mu  = base[tid] * inv_n;
        float var = base[64 + tid] * inv_n - mu * mu;
        smu[tid] = mu;
        ssc[tid] = rsqrtf(var + BN_EPS) * gamma[tid];
    }
    __syncthreads();
    int idx = blockIdx.x * 256 + tid;
    int cq  = idx & 15;
    float4 a  = ((const float4*)g_agg)[idx];
    float4 x  = ((float4*)g_x)[idx];
    float4 mu = ((const float4*)smu)[cq];
    float4 sc = ((const float4*)ssc)[cq];
    float4 bt = ((const float4*)beta)[cq];
    x.x += fmaxf((a.x - mu.x) * sc.x + bt.x, 0.0f);
    x.y += fmaxf((a.y - mu.y) * sc.y + bt.y, 0.0f);
    x.z += fmaxf((a.z - mu.z) * sc.z + bt.z, 0.0f);
    x.w += fmaxf((a.w - mu.w) * sc.w + bt.w, 0.0f);
    ((float4*)g_x)[idx] = x;
}

// ---------------- decoder with fused final BN apply --------------------------
__global__ __launch_bounds__(256) void k_decode(const int* __restrict__ pred,
                                                const float* __restrict__ gamma,
                                                const float* __restrict__ beta,
                                                float* __restrict__ out,
                                                int layer) {
    __shared__ float smu[64], ssc[64], sbt[64];
    int tid = threadIdx.x;
    if (tid < 64) {
        const float* base = P_SUMS + layer * 128;
        const float inv_n = 1.0f / (float)N_NODES;
        float mu  = base[tid] * inv_n;
        float var = base[64 + tid] * inv_n - mu * mu;
        smu[tid] = mu;
        ssc[tid] = rsqrtf(var + BN_EPS) * gamma[tid];
        sbt[tid] = beta[tid];
    }
    __syncthreads();
    int gid = blockIdx.x * 256 + tid;
    int p = gid >> 4;
    int l = gid & 15;
    int a = pred[2 * p];
    int b = pred[2 * p + 1];
    float4 mu = ((const float4*)smu)[l];
    float4 sc = ((const float4*)ssc)[l];
    float4 bt = ((const float4*)sbt)[l];

    float4 xa = ((const float4*)g_x)[a * 16 + l];
    float4 ga = ((const float4*)g_agg)[a * 16 + l];
    float4 za = make_float4(
        xa.x + fmaxf((ga.x - mu.x) * sc.x + bt.x, 0.0f),
        xa.y + fmaxf((ga.y - mu.y) * sc.y + bt.y, 0.0f),
        xa.z + fmaxf((ga.z - mu.z) * sc.z + bt.z, 0.0f),
        xa.w + fmaxf((ga.w - mu.w) * sc.w + bt.w, 0.0f));
    float4 xb = ((const float4*)g_x)[b * 16 + l];
    float4 gb = ((const float4*)g_agg)[b * 16 + l];
    float4 zb = make_float4(
        xb.x + fmaxf((gb.x - mu.x) * sc.x + bt.x, 0.0f),
        xb.y + fmaxf((gb.y - mu.y) * sc.y + bt.y, 0.0f),
        xb.z + fmaxf((gb.z - mu.z) * sc.z + bt.z, 0.0f),
        xb.w + fmaxf((gb.w - mu.w) * sc.w + bt.w, 0.0f));

    float s = za.x * zb.x + za.y * zb.y + za.z * zb.z + za.w * zb.w;
    s += __shfl_xor_sync(0xffffffffu, s, 8);
    s += __shfl_xor_sync(0xffffffffu, s, 4);
    s += __shfl_xor_sync(0xffffffffu, s, 2);
    s += __shfl_xor_sync(0xffffffffu, s, 1);
    if (l == 0) out[p] = s;
}

// ---------------- launch ------------------------------------------------------
extern "C" void kernel_launch(void* const* d_in, const int* in_sizes, int n_in,
                              void* d_out, int out_size) {
    const int*   edge    = (const int*)  d_in[0];
    const int*   pred    = (const int*)  d_in[1];
    const float* id_emb  = (const float*)d_in[2];
    const float* n2v     = (const float*)d_in[3];
    const float* proj_w  = (const float*)d_in[4];
    const float* proj_b  = (const float*)d_in[5];
    const float* conv_w  = (const float*)d_in[6];
    const float* conv_b  = (const float*)d_in[7];
    const float* gamma   = (const float*)d_in[8];
    const float* beta    = (const float*)d_in[9];
    float* out = (float*)d_out;

    void* zp = nullptr;
    cudaGetSymbolAddress(&zp, g_zb);
    cudaMemsetAsync(zp, 0, ZB_INTS * sizeof(int));

    const int NB_E = (NE + 255) / 256;
    const int NB_S = (N_NODES + 255) / 256;

    k_count<<<NB_E, 256>>>(edge + NE);
    k_scan <<<NB_S, 256>>>();
    k_fill <<<NB_E, 256>>>(edge, edge + NE);
    k_proj <<<(N_NODES + 255) / 256, 256>>>(id_emb, n2v, proj_w, proj_b);

    k_gg    <<<N_NODES / 16, 256>>>(conv_w,             conv_b,       0);
    k_apply <<<N_NODES * 16 / 256, 256>>>(gamma,        beta,         0);
    k_gg    <<<N_NODES / 16, 256>>>(conv_w + HID * HID, conv_b + HID, 1);
    k_decode<<<NPRED * 16 / 256, 256>>>(pred, gamma + HID, beta + HID, out, 1);
}